// round 1
// baseline (speedup 1.0000x reference)
#include <cuda_runtime.h>

// GraphConvDown: per-edge MLP (C_in+3 -> 64 -> 64) + scatter-max onto M sampled points.
// Round 1 baseline: thread-per-edge fp32, weights in SMEM, atomicMax aggregation.
//
// Output layout (concatenated, float32):
//   out[0 .. 4*M)            : new_bxyz  [M,4]
//   out[4*M .. 4*M + 64*M)   : new_feat  [M,64]

#define C_OUT 64

// ---------------------------------------------------------------------------
// Kernel 1: gather new_bxyz and zero the feature-aggregation region.
// (d_out is poisoned 0xAA before timing; agg must start at 0.0f. All MLP
//  outputs are ReLU >= 0, so max-with-0 init reproduces the reference's
//  isfinite->0 handling for isolated nodes exactly.)
// ---------------------------------------------------------------------------
__global__ void init_kernel(const float4* __restrict__ bxyz4,
                            const int* __restrict__ sample_idx,
                            float* __restrict__ out, int M) {
    int i = blockIdx.x * blockDim.x + threadIdx.x;
    if (i < M) {
        int s = sample_idx[i];
        ((float4*)out)[i] = bxyz4[s];           // new_bxyz[i] = point_bxyz[sample_idx[i]]
    }
    // zero feat region: M*64 floats = M*16 float4
    float4* fz = (float4*)(out + 4 * (size_t)M);
    int total4 = M * (C_OUT / 4);
    int stride = gridDim.x * blockDim.x;
    for (int j = i; j < total4; j += stride)
        fz[j] = make_float4(0.f, 0.f, 0.f, 0.f);
}

// ---------------------------------------------------------------------------
// Kernel 2: one thread per edge. Gather features + rel pos, 2-layer MLP,
// atomicMax scatter (int-reinterpret trick valid for non-negative floats).
// ---------------------------------------------------------------------------
__global__ __launch_bounds__(128, 3)
void edge_kernel(const float4* __restrict__ bxyz4,
                 const float4* __restrict__ feat4,     // point_feat as [N][8] float4
                 const int*    __restrict__ e_point,
                 const int*    __restrict__ e_new,
                 const float*  __restrict__ W1,        // [35][64]
                 const float*  __restrict__ b1,        // [64]
                 const float*  __restrict__ W2,        // [64][64]
                 const float*  __restrict__ b2,        // [64]
                 const float4* __restrict__ newb4,     // d_out bxyz region [M] float4
                 int*          __restrict__ outf_i,    // d_out feat region as int*
                 int E)
{
    __shared__ float4 W1s[35 * 16];   // W1[k][c], 16 float4 per row
    __shared__ float4 W2s[64 * 16];   // W2[k][c]
    __shared__ float  b1s[64], b2s[64];

    for (int i = threadIdx.x; i < 35 * 16; i += blockDim.x) W1s[i] = ((const float4*)W1)[i];
    for (int i = threadIdx.x; i < 64 * 16; i += blockDim.x) W2s[i] = ((const float4*)W2)[i];
    if (threadIdx.x < 64) { b1s[threadIdx.x] = b1[threadIdx.x]; b2s[threadIdx.x] = b2[threadIdx.x]; }
    __syncthreads();

    int e = blockIdx.x * blockDim.x + threadIdx.x;
    if (e >= E) return;

    int p = e_point[e];
    int m = e_new[e];

    float4 pb = bxyz4[p];
    float4 nb = newb4[m];

    // edge feature: 32 gathered feats + 3 relative xyz (col 0 is batch idx)
    float ef[35];
    const float4* fp = feat4 + (size_t)p * 8;
    #pragma unroll
    for (int q = 0; q < 8; q++) {
        float4 v = fp[q];
        ef[4*q + 0] = v.x; ef[4*q + 1] = v.y; ef[4*q + 2] = v.z; ef[4*q + 3] = v.w;
    }
    ef[32] = pb.y - nb.y;
    ef[33] = pb.z - nb.z;
    ef[34] = pb.w - nb.w;

    // ---- Layer 1: h = relu(ef @ W1 + b1) ---- (fully unrolled so h[] stays in regs)
    float h[64];
    #pragma unroll
    for (int c = 0; c < 64; c++) h[c] = b1s[c];
    #pragma unroll
    for (int k = 0; k < 35; k++) {
        float v = ef[k];
        #pragma unroll
        for (int c4 = 0; c4 < 16; c4++) {
            float4 w = W1s[k * 16 + c4];
            h[4*c4 + 0] += v * w.x;
            h[4*c4 + 1] += v * w.y;
            h[4*c4 + 2] += v * w.z;
            h[4*c4 + 3] += v * w.w;
        }
    }
    #pragma unroll
    for (int c = 0; c < 64; c++) h[c] = fmaxf(h[c], 0.f);

    // ---- Layer 2 + relu + scatter-max, tiled 8 output cols at a time ----
    int* outm = outf_i + (size_t)m * 64;
    #pragma unroll 1
    for (int ct = 0; ct < 8; ct++) {
        float g[8];
        #pragma unroll
        for (int j = 0; j < 8; j++) g[j] = b2s[ct * 8 + j];
        #pragma unroll
        for (int k = 0; k < 64; k++) {
            float v = h[k];
            float4 wa = W2s[k * 16 + ct * 2 + 0];
            float4 wb = W2s[k * 16 + ct * 2 + 1];
            g[0] += v * wa.x; g[1] += v * wa.y; g[2] += v * wa.z; g[3] += v * wa.w;
            g[4] += v * wb.x; g[5] += v * wb.y; g[6] += v * wb.z; g[7] += v * wb.w;
        }
        #pragma unroll
        for (int j = 0; j < 8; j++) {
            float r = fmaxf(g[j], 0.f);
            // non-negative float: IEEE bit pattern is monotone as signed int
            atomicMax(outm + ct * 8 + j, __float_as_int(r));
        }
    }
}

// ---------------------------------------------------------------------------
extern "C" void kernel_launch(void* const* d_in, const int* in_sizes, int n_in,
                              void* d_out, int out_size)
{
    const float* point_bxyz = (const float*)d_in[0];   // [N,4]
    const float* point_feat = (const float*)d_in[1];   // [N,32]
    const int*   sample_idx = (const int*)  d_in[2];   // [M]
    const int*   e_point    = (const int*)  d_in[3];   // [E]
    const int*   e_new      = (const int*)  d_in[4];   // [E]
    const float* W1         = (const float*)d_in[5];   // [35,64]
    const float* b1         = (const float*)d_in[6];   // [64]
    const float* W2         = (const float*)d_in[7];   // [64,64]
    const float* b2         = (const float*)d_in[8];   // [64]

    float* out = (float*)d_out;
    int M = in_sizes[2];
    int E = in_sizes[3];

    init_kernel<<<(M + 127) / 128, 128>>>(
        (const float4*)point_bxyz, sample_idx, out, M);

    edge_kernel<<<(E + 127) / 128, 128>>>(
        (const float4*)point_bxyz, (const float4*)point_feat,
        e_point, e_new, W1, b1, W2, b2,
        (const float4*)out,                    // new_bxyz (written by init_kernel)
        (int*)(out + 4 * (size_t)M),           // feat agg region
        E);
}

// round 2
// speedup vs baseline: 1.0049x; 1.0049x over previous
#include <cuda_runtime.h>

// GraphConvDown: per-edge MLP (35 -> 64 -> 64) + scatter-max onto M sampled points.
// Round 2: counting-sort edges by destination, chunked register-max aggregation
// (atomics only at segment boundaries), packed f32x2 FFMA for the MLP.
//
// Output layout (float32): out[0..4M) = new_bxyz [M,4]; out[4M..4M+64M) = new_feat [M,64]

#define C_OUT 64
#define K1 35
#define CHUNK 16
#define MAXM 131072
#define MAXE 2000128
#define SCAN_BLK 1024

typedef unsigned long long ull;

// ---------- static scratch (no allocations allowed) ----------
__device__ int  g_cnt[MAXM];
__device__ int  g_incl[MAXM];
__device__ int  g_cursor[MAXM];
__device__ int  g_bsum[256];
__device__ int  g_btop[256];
__device__ int2 g_sorted[MAXE];     // (e_point, e_new) sorted by e_new

// ---------- f32x2 helpers ----------
__device__ __forceinline__ ull ffma2(ull a, ull b, ull c) {
    ull d;
    asm("fma.rn.f32x2 %0, %1, %2, %3;" : "=l"(d) : "l"(a), "l"(b), "l"(c));
    return d;
}
__device__ __forceinline__ ull splat(float x) {
    ull r;
    asm("mov.b64 %0, {%1, %1};" : "=l"(r) : "f"(x));
    return r;
}
__device__ __forceinline__ void unpack2(ull v, float& lo, float& hi) {
    asm("mov.b64 {%0, %1}, %2;" : "=f"(lo), "=f"(hi) : "l"(v));
}

// ---------------------------------------------------------------------------
// K1: gather new_bxyz, zero feat region, zero histogram
// ---------------------------------------------------------------------------
__global__ void k_init(const float4* __restrict__ bxyz4,
                       const int* __restrict__ sample_idx,
                       float* __restrict__ out, int M) {
    int i = blockIdx.x * blockDim.x + threadIdx.x;
    int stride = gridDim.x * blockDim.x;
    float4* ob = (float4*)out;
    for (int j = i; j < M; j += stride) {
        ob[j] = bxyz4[sample_idx[j]];
        g_cnt[j] = 0;
    }
    float4* fz = (float4*)(out + 4 * (size_t)M);
    int tot = M * 16;
    for (int j = i; j < tot; j += stride)
        fz[j] = make_float4(0.f, 0.f, 0.f, 0.f);
}

// ---------------------------------------------------------------------------
// K2: histogram of e_new
// ---------------------------------------------------------------------------
__global__ void k_hist(const int* __restrict__ e_new, int E) {
    int i = blockIdx.x * blockDim.x + threadIdx.x;
    if (i < E) atomicAdd(&g_cnt[e_new[i]], 1);
}

// ---------------------------------------------------------------------------
// K3a/b/c: exclusive scan of g_cnt -> g_cursor
// ---------------------------------------------------------------------------
__global__ void k_scan1(int M) {
    __shared__ int sh[SCAN_BLK];
    int i = blockIdx.x * SCAN_BLK + threadIdx.x;
    int v = (i < M) ? g_cnt[i] : 0;
    sh[threadIdx.x] = v;
    __syncthreads();
    for (int d = 1; d < SCAN_BLK; d <<= 1) {
        int t = (threadIdx.x >= d) ? sh[threadIdx.x - d] : 0;
        __syncthreads();
        sh[threadIdx.x] += t;
        __syncthreads();
    }
    if (i < M) g_incl[i] = sh[threadIdx.x];
    if (threadIdx.x == SCAN_BLK - 1) g_bsum[blockIdx.x] = sh[SCAN_BLK - 1];
}
__global__ void k_scan2(int NB) {
    __shared__ int sh[256];
    int v = (threadIdx.x < NB) ? g_bsum[threadIdx.x] : 0;
    sh[threadIdx.x] = v;
    __syncthreads();
    for (int d = 1; d < 256; d <<= 1) {
        int t = (threadIdx.x >= d) ? sh[threadIdx.x - d] : 0;
        __syncthreads();
        sh[threadIdx.x] += t;
        __syncthreads();
    }
    g_btop[threadIdx.x] = sh[threadIdx.x] - v;   // exclusive
}
__global__ void k_scan3(int M) {
    int i = blockIdx.x * blockDim.x + threadIdx.x;
    if (i < M)
        g_cursor[i] = g_incl[i] - g_cnt[i] + g_btop[i >> 10];
}

// ---------------------------------------------------------------------------
// K4: scatter edges into destination-sorted order
// ---------------------------------------------------------------------------
__global__ void k_scatter(const int* __restrict__ e_point,
                          const int* __restrict__ e_new, int E) {
    int i = blockIdx.x * blockDim.x + threadIdx.x;
    if (i < E) {
        int m = e_new[i];
        int pos = atomicAdd(&g_cursor[m], 1);
        g_sorted[pos] = make_int2(e_point[i], m);
    }
}

// ---------------------------------------------------------------------------
// K5: main — chunk of CHUNK sorted edges per thread; MLP in f32x2;
// register running-max; atomicMax flush only at segment/chunk boundaries.
// ---------------------------------------------------------------------------
__global__ __launch_bounds__(128)
void k_main(const float4* __restrict__ bxyz4,
            const float4* __restrict__ feat4,
            const float*  __restrict__ W1, const float* __restrict__ b1,
            const float*  __restrict__ W2, const float* __restrict__ b2,
            const float4* __restrict__ newb4,
            int*          __restrict__ outf,
            int E)
{
    __shared__ __align__(16) float W1s[K1 * 64];
    __shared__ __align__(16) float W2s[64 * 64];
    __shared__ __align__(16) float b1s[64], b2s[64];

    for (int i = threadIdx.x; i < K1 * 16; i += blockDim.x)
        ((float4*)W1s)[i] = ((const float4*)W1)[i];
    for (int i = threadIdx.x; i < 64 * 16; i += blockDim.x)
        ((float4*)W2s)[i] = ((const float4*)W2)[i];
    if (threadIdx.x < 64) { b1s[threadIdx.x] = b1[threadIdx.x]; b2s[threadIdx.x] = b2[threadIdx.x]; }
    __syncthreads();

    const ulonglong2* W1v = (const ulonglong2*)W1s;  // row k: 16 x ulonglong2
    const ulonglong2* W2v = (const ulonglong2*)W2s;
    const ull* b1v = (const ull*)b1s;
    const ull* b2v = (const ull*)b2s;

    int t = blockIdx.x * blockDim.x + threadIdx.x;
    int start = t * CHUNK;
    if (start >= E) return;
    int end = min(start + CHUNK, E);

    float acc[64];
    #pragma unroll
    for (int c = 0; c < 64; c++) acc[c] = 0.f;
    int cur_m = -1;
    float4 nb = make_float4(0.f, 0.f, 0.f, 0.f);

    #pragma unroll 1
    for (int pos = start; pos < end; pos++) {
        int2 em = g_sorted[pos];

        if (em.y != cur_m) {
            if (cur_m >= 0) {
                int* om = outf + (size_t)cur_m * 64;
                #pragma unroll
                for (int c = 0; c < 64; c++)
                    atomicMax(om + c, __float_as_int(acc[c]));
                #pragma unroll
                for (int c = 0; c < 64; c++) acc[c] = 0.f;
            }
            cur_m = em.y;
            nb = newb4[cur_m];
        }

        int p = em.x;
        float4 pb = bxyz4[p];
        const float4* fp = feat4 + (size_t)p * 8;

        // ---- layer 1: h2 = b1 + ef @ W1 (pair-packed) ----
        ull h2[32];
        #pragma unroll
        for (int i = 0; i < 32; i++) h2[i] = b1v[i];

        #pragma unroll
        for (int q = 0; q < 8; q++) {
            float4 v = fp[q];
            ull s0 = splat(v.x), s1 = splat(v.y), s2 = splat(v.z), s3 = splat(v.w);
            const ulonglong2* r0 = W1v + (4 * q + 0) * 16;
            const ulonglong2* r1 = W1v + (4 * q + 1) * 16;
            const ulonglong2* r2 = W1v + (4 * q + 2) * 16;
            const ulonglong2* r3 = W1v + (4 * q + 3) * 16;
            #pragma unroll
            for (int i = 0; i < 16; i++) {
                ulonglong2 w;
                w = r0[i]; h2[2*i] = ffma2(s0, w.x, h2[2*i]); h2[2*i+1] = ffma2(s0, w.y, h2[2*i+1]);
                w = r1[i]; h2[2*i] = ffma2(s1, w.x, h2[2*i]); h2[2*i+1] = ffma2(s1, w.y, h2[2*i+1]);
                w = r2[i]; h2[2*i] = ffma2(s2, w.x, h2[2*i]); h2[2*i+1] = ffma2(s2, w.y, h2[2*i+1]);
                w = r3[i]; h2[2*i] = ffma2(s3, w.x, h2[2*i]); h2[2*i+1] = ffma2(s3, w.y, h2[2*i+1]);
            }
        }
        {   // relative position (xyz)
            ull sx = splat(pb.y - nb.y), sy = splat(pb.z - nb.z), sz = splat(pb.w - nb.w);
            const ulonglong2* r0 = W1v + 32 * 16;
            const ulonglong2* r1 = W1v + 33 * 16;
            const ulonglong2* r2 = W1v + 34 * 16;
            #pragma unroll
            for (int i = 0; i < 16; i++) {
                ulonglong2 w;
                w = r0[i]; h2[2*i] = ffma2(sx, w.x, h2[2*i]); h2[2*i+1] = ffma2(sx, w.y, h2[2*i+1]);
                w = r1[i]; h2[2*i] = ffma2(sy, w.x, h2[2*i]); h2[2*i+1] = ffma2(sy, w.y, h2[2*i+1]);
                w = r2[i]; h2[2*i] = ffma2(sz, w.x, h2[2*i]); h2[2*i+1] = ffma2(sz, w.y, h2[2*i+1]);
            }
        }

        // ---- layer 2: g2 = b2 + relu(h) @ W2 (pair-packed) ----
        ull g2[32];
        #pragma unroll
        for (int i = 0; i < 32; i++) g2[i] = b2v[i];

        #pragma unroll
        for (int kk = 0; kk < 32; kk++) {
            float x, y;
            unpack2(h2[kk], x, y);
            x = fmaxf(x, 0.f); y = fmaxf(y, 0.f);
            ull sx = splat(x), sy = splat(y);
            const ulonglong2* ra = W2v + (2 * kk + 0) * 16;
            const ulonglong2* rb = W2v + (2 * kk + 1) * 16;
            #pragma unroll
            for (int i = 0; i < 16; i++) {
                ulonglong2 w;
                w = ra[i]; g2[2*i] = ffma2(sx, w.x, g2[2*i]); g2[2*i+1] = ffma2(sx, w.y, g2[2*i+1]);
                w = rb[i]; g2[2*i] = ffma2(sy, w.x, g2[2*i]); g2[2*i+1] = ffma2(sy, w.y, g2[2*i+1]);
            }
        }

        // ---- running max (acc >= 0 so relu is implicit) ----
        #pragma unroll
        for (int i = 0; i < 32; i++) {
            float x, y;
            unpack2(g2[i], x, y);
            acc[2*i]   = fmaxf(acc[2*i],   x);
            acc[2*i+1] = fmaxf(acc[2*i+1], y);
        }
    }

    if (cur_m >= 0) {
        int* om = outf + (size_t)cur_m * 64;
        #pragma unroll
        for (int c = 0; c < 64; c++)
            atomicMax(om + c, __float_as_int(acc[c]));
    }
}

// ---------------------------------------------------------------------------
extern "C" void kernel_launch(void* const* d_in, const int* in_sizes, int n_in,
                              void* d_out, int out_size)
{
    const float* point_bxyz = (const float*)d_in[0];
    const float* point_feat = (const float*)d_in[1];
    const int*   sample_idx = (const int*)  d_in[2];
    const int*   e_point    = (const int*)  d_in[3];
    const int*   e_new      = (const int*)  d_in[4];
    const float* W1         = (const float*)d_in[5];
    const float* b1         = (const float*)d_in[6];
    const float* W2         = (const float*)d_in[7];
    const float* b2         = (const float*)d_in[8];

    float* out = (float*)d_out;
    int M = in_sizes[2];
    int E = in_sizes[3];

    k_init<<<1024, 256>>>((const float4*)point_bxyz, sample_idx, out, M);
    k_hist<<<(E + 255) / 256, 256>>>(e_new, E);

    int NB = (M + SCAN_BLK - 1) / SCAN_BLK;
    k_scan1<<<NB, SCAN_BLK>>>(M);
    k_scan2<<<1, 256>>>(NB);
    k_scan3<<<(M + 255) / 256, 256>>>(M);

    k_scatter<<<(E + 255) / 256, 256>>>(e_point, e_new, E);

    int T = (E + CHUNK - 1) / CHUNK;
    k_main<<<(T + 127) / 128, 128>>>(
        (const float4*)point_bxyz, (const float4*)point_feat,
        W1, b1, W2, b2,
        (const float4*)out,
        (int*)(out + 4 * (size_t)M),
        E);
}